// round 2
// baseline (speedup 1.0000x reference)
#include <cuda_runtime.h>

#define N_NODES 50000
#define N_EDGES 800000
#define IN_DIM 96
#define HID 32
#define OUT_DIM 64

// Scratch (device globals: allocation-free rule)
__device__ __align__(16) float g_xl[N_NODES * HID];        // x @ W1l
__device__ __align__(16) float g_hself[N_NODES * HID];     // x @ W1r + b1
__device__ __align__(16) float g_agg1[N_NODES * HID];      // segment-sum of g_xl
__device__ __align__(16) float g_h[N_NODES * HID];         // relu(agg1/cnt + hself)
__device__ __align__(16) float g_hl[N_NODES * OUT_DIM];    // h @ W2l
__device__ __align__(16) float g_hself2[N_NODES * OUT_DIM];// h @ W2r + b2
__device__ __align__(16) float g_agg2[N_NODES * OUT_DIM];  // segment-sum of g_hl
__device__ float g_cnt[N_NODES];

// ---------------------------------------------------------------------------
__global__ void k_zero() {
    int i = blockIdx.x * blockDim.x + threadIdx.x;
    int stride = gridDim.x * blockDim.x;
    float4 z = make_float4(0.f, 0.f, 0.f, 0.f);
    float4* a1 = (float4*)g_agg1;
    float4* a2 = (float4*)g_agg2;
    for (int j = i; j < N_NODES * HID / 4; j += stride) a1[j] = z;
    for (int j = i; j < N_NODES * OUT_DIM / 4; j += stride) a2[j] = z;
    for (int j = i; j < N_NODES; j += stride) g_cnt[j] = 0.f;
}

// ---------------------------------------------------------------------------
// GEMM1: [N,96] x [96,32] (two weight matrices). Block = 256 thr = 32 cols x
// 8 warps, each thread does 4 rows -> 32 rows/block. Weights in smem.
__global__ void k_gemm1(const float* __restrict__ x,
                        const float* __restrict__ Wl,
                        const float* __restrict__ Wr,
                        const float* __restrict__ b) {
    __shared__ float sL[IN_DIM * HID];
    __shared__ float sR[IN_DIM * HID];
    __shared__ float sb[HID];
    int t = threadIdx.x;
    for (int i = t; i < IN_DIM * HID; i += 256) { sL[i] = Wl[i]; sR[i] = Wr[i]; }
    if (t < HID) sb[t] = b[t];
    __syncthreads();

    int col  = t & 31;
    int wy   = t >> 5;                 // 0..7
    int row0 = blockIdx.x * 32 + wy * 4;

    float aL[4], aR[4];
    int rr[4];
#pragma unroll
    for (int r = 0; r < 4; r++) {
        aL[r] = 0.f; aR[r] = sb[col];
        rr[r] = min(row0 + r, N_NODES - 1);   // clamp reads; guard stores
    }
#pragma unroll 4
    for (int k = 0; k < IN_DIM; k++) {
        float wl = sL[k * HID + col];
        float wr = sR[k * HID + col];
#pragma unroll
        for (int r = 0; r < 4; r++) {
            float xv = x[rr[r] * IN_DIM + k];   // warp-uniform -> broadcast
            aL[r] += xv * wl;
            aR[r] += xv * wr;
        }
    }
#pragma unroll
    for (int r = 0; r < 4; r++) {
        int row = row0 + r;
        if (row < N_NODES) {
            g_xl[row * HID + col]    = aL[r];
            g_hself[row * HID + col] = aR[r];
        }
    }
}

// ---------------------------------------------------------------------------
// scatter1: 8 threads per edge, each moves one float4 (HID=32 floats/row).
// edge_index is int32 (JAX x64 disabled downcasts the int64 request).
__global__ void k_scatter1(const int* __restrict__ ei) {
    int t = blockIdx.x * blockDim.x + threadIdx.x;
    int e = t >> 3;
    if (e >= N_EDGES) return;
    int lane = t & 7;
    int src = ei[e];
    int dst = ei[N_EDGES + e];
    float4 v = ((const float4*)g_xl)[src * 8 + lane];
    atomicAdd(((float4*)g_agg1) + dst * 8 + lane, v);
    if (lane == 0) atomicAdd(&g_cnt[dst], 1.0f);
}

// ---------------------------------------------------------------------------
__global__ void k_finish1() {
    int i = blockIdx.x * blockDim.x + threadIdx.x;
    int stride = gridDim.x * blockDim.x;
    for (int j = i; j < N_NODES * HID; j += stride) {
        int row = j >> 5;
        float inv = 1.0f / fmaxf(g_cnt[row], 1.0f);
        float v = g_agg1[j] * inv + g_hself[j];
        g_h[j] = v > 0.f ? v : 0.f;
    }
}

// ---------------------------------------------------------------------------
// GEMM2: [N,32] x [32,64] (two matrices). Block = 256 thr = 64 cols x 4 warp-
// pairs, 4 rows/thread -> 16 rows/block. 50000/16 = 3125 exactly, no guard.
__global__ void k_gemm2(const float* __restrict__ Wl,
                        const float* __restrict__ Wr,
                        const float* __restrict__ b) {
    __shared__ float sL[HID * OUT_DIM];
    __shared__ float sR[HID * OUT_DIM];
    __shared__ float sb[OUT_DIM];
    int t = threadIdx.x;
    for (int i = t; i < HID * OUT_DIM; i += 256) { sL[i] = Wl[i]; sR[i] = Wr[i]; }
    if (t < OUT_DIM) sb[t] = b[t];
    __syncthreads();

    int col  = t & 63;
    int wy   = t >> 6;                  // 0..3
    int row0 = blockIdx.x * 16 + wy * 4;

    float aL[4], aR[4];
#pragma unroll
    for (int r = 0; r < 4; r++) { aL[r] = 0.f; aR[r] = sb[col]; }
#pragma unroll 4
    for (int k = 0; k < HID; k++) {
        float wl = sL[k * OUT_DIM + col];
        float wr = sR[k * OUT_DIM + col];
#pragma unroll
        for (int r = 0; r < 4; r++) {
            float hv = g_h[(row0 + r) * HID + k];   // warp-uniform
            aL[r] += hv * wl;
            aR[r] += hv * wr;
        }
    }
#pragma unroll
    for (int r = 0; r < 4; r++) {
        int row = row0 + r;
        g_hl[row * OUT_DIM + col]     = aL[r];
        g_hself2[row * OUT_DIM + col] = aR[r];
    }
}

// ---------------------------------------------------------------------------
// scatter2: 16 threads per edge, each moves one float4 (OUT=64 floats/row).
__global__ void k_scatter2(const int* __restrict__ ei) {
    int t = blockIdx.x * blockDim.x + threadIdx.x;
    int e = t >> 4;
    if (e >= N_EDGES) return;
    int lane = t & 15;
    int src = ei[e];
    int dst = ei[N_EDGES + e];
    float4 v = ((const float4*)g_hl)[src * 16 + lane];
    atomicAdd(((float4*)g_agg2) + dst * 16 + lane, v);
}

// ---------------------------------------------------------------------------
__global__ void k_final(float* __restrict__ out) {
    int i = blockIdx.x * blockDim.x + threadIdx.x;
    int stride = gridDim.x * blockDim.x;
    for (int j = i; j < N_NODES * OUT_DIM; j += stride) {
        int row = j >> 6;
        float inv = 1.0f / fmaxf(g_cnt[row], 1.0f);
        out[j] = g_agg2[j] * inv + g_hself2[j];
    }
}

// ---------------------------------------------------------------------------
extern "C" void kernel_launch(void* const* d_in, const int* in_sizes, int n_in,
                              void* d_out, int out_size) {
    const float* x   = (const float*)d_in[0];
    const int*   ei  = (const int*)d_in[1];
    const float* W1l = (const float*)d_in[2];
    const float* W1r = (const float*)d_in[3];
    const float* b1  = (const float*)d_in[4];
    const float* W2l = (const float*)d_in[5];
    const float* W2r = (const float*)d_in[6];
    const float* b2  = (const float*)d_in[7];
    float* out = (float*)d_out;

    k_zero<<<2048, 256>>>();
    k_gemm1<<<(N_NODES + 31) / 32, 256>>>(x, W1l, W1r, b1);
    k_scatter1<<<(N_EDGES * 8 + 255) / 256, 256>>>(ei);
    k_finish1<<<2048, 256>>>();
    k_gemm2<<<N_NODES / 16, 256>>>(W2l, W2r, b2);
    k_scatter2<<<(N_EDGES * 16 + 255) / 256, 256>>>(ei);
    k_final<<<2048, 256>>>(out);
}

// round 3
// speedup vs baseline: 1.1769x; 1.1769x over previous
#include <cuda_runtime.h>

#define N_NODES 50000
#define N_EDGES 800000
#define IN_DIM 96
#define HID 32
#define OUT_DIM 64

// Scratch (device globals: allocation-free rule)
__device__ __align__(16) float g_xl[N_NODES * HID];        // x @ W1l
__device__ __align__(16) float g_hself[N_NODES * HID];     // x @ W1r + b1
__device__ __align__(16) float g_agg1[N_NODES * HID];      // segment-sum of g_xl
__device__ __align__(16) float g_h[N_NODES * HID];         // relu(agg1/cnt + hself)
__device__ __align__(16) float g_agg2[N_NODES * HID];      // segment-sum of g_h (32-dim!)
__device__ float g_cnt[N_NODES];

// ---------------------------------------------------------------------------
__global__ void k_zero() {
    int i = blockIdx.x * blockDim.x + threadIdx.x;
    int stride = gridDim.x * blockDim.x;
    float4 z = make_float4(0.f, 0.f, 0.f, 0.f);
    float4* a1 = (float4*)g_agg1;
    float4* a2 = (float4*)g_agg2;
    for (int j = i; j < N_NODES * HID / 4; j += stride) { a1[j] = z; a2[j] = z; }
    for (int j = i; j < N_NODES; j += stride) g_cnt[j] = 0.f;
}

// ---------------------------------------------------------------------------
// GEMM1: [N,96] x [96,32] (two weight matrices). Block = 256 thr = 32 cols x
// 8 warps, each thread does 4 rows -> 32 rows/block. Weights in smem.
__global__ void k_gemm1(const float* __restrict__ x,
                        const float* __restrict__ Wl,
                        const float* __restrict__ Wr,
                        const float* __restrict__ b) {
    __shared__ float sL[IN_DIM * HID];
    __shared__ float sR[IN_DIM * HID];
    __shared__ float sb[HID];
    int t = threadIdx.x;
    for (int i = t; i < IN_DIM * HID; i += 256) { sL[i] = Wl[i]; sR[i] = Wr[i]; }
    if (t < HID) sb[t] = b[t];
    __syncthreads();

    int col  = t & 31;
    int wy   = t >> 5;                 // 0..7
    int row0 = blockIdx.x * 32 + wy * 4;

    float aL[4], aR[4];
    int rr[4];
#pragma unroll
    for (int r = 0; r < 4; r++) {
        aL[r] = 0.f; aR[r] = sb[col];
        rr[r] = min(row0 + r, N_NODES - 1);   // clamp reads; guard stores
    }
#pragma unroll 4
    for (int k = 0; k < IN_DIM; k++) {
        float wl = sL[k * HID + col];
        float wr = sR[k * HID + col];
#pragma unroll
        for (int r = 0; r < 4; r++) {
            float xv = x[rr[r] * IN_DIM + k];   // warp-uniform -> broadcast
            aL[r] += xv * wl;
            aR[r] += xv * wr;
        }
    }
#pragma unroll
    for (int r = 0; r < 4; r++) {
        int row = row0 + r;
        if (row < N_NODES) {
            g_xl[row * HID + col]    = aL[r];
            g_hself[row * HID + col] = aR[r];
        }
    }
}

// ---------------------------------------------------------------------------
// scatter1: 8 threads per edge, each moves one float4 (HID=32 floats/row).
// edge_index is int32 (JAX x64 disabled downcasts the int64 request).
__global__ void k_scatter1(const int* __restrict__ ei) {
    int t = blockIdx.x * blockDim.x + threadIdx.x;
    int e = t >> 3;
    if (e >= N_EDGES) return;
    int lane = t & 7;
    int src = ei[e];
    int dst = ei[N_EDGES + e];
    float4 v = ((const float4*)g_xl)[src * 8 + lane];
    atomicAdd(((float4*)g_agg1) + dst * 8 + lane, v);
    if (lane == 0) atomicAdd(&g_cnt[dst], 1.0f);
}

// ---------------------------------------------------------------------------
__global__ void k_finish1() {
    int i = blockIdx.x * blockDim.x + threadIdx.x;
    int stride = gridDim.x * blockDim.x;
    for (int j = i; j < N_NODES * HID; j += stride) {
        int row = j >> 5;
        float inv = 1.0f / fmaxf(g_cnt[row], 1.0f);
        float v = g_agg1[j] * inv + g_hself[j];
        g_h[j] = v > 0.f ? v : 0.f;
    }
}

// ---------------------------------------------------------------------------
// scatter2: 8 threads per edge, 32-dim h rows (project-after-aggregate).
__global__ void k_scatter2(const int* __restrict__ ei) {
    int t = blockIdx.x * blockDim.x + threadIdx.x;
    int e = t >> 3;
    if (e >= N_EDGES) return;
    int lane = t & 7;
    int src = ei[e];
    int dst = ei[N_EDGES + e];
    float4 v = ((const float4*)g_h)[src * 8 + lane];
    atomicAdd(((float4*)g_agg2) + dst * 8 + lane, v);
}

// ---------------------------------------------------------------------------
// Fused layer-2 GEMM + epilogue:
//   out = (agg2/cnt) @ W2l + h @ W2r + b2
// Block = 256 thr = 64 cols x 4 warp-pairs, 4 rows/thread -> 16 rows/block.
// 50000/16 = 3125 exactly, no guard.
__global__ void k_gemm2_final(const float* __restrict__ Wl,
                              const float* __restrict__ Wr,
                              const float* __restrict__ b,
                              float* __restrict__ out) {
    __shared__ float sL[HID * OUT_DIM];
    __shared__ float sR[HID * OUT_DIM];
    __shared__ float sb[OUT_DIM];
    int t = threadIdx.x;
    for (int i = t; i < HID * OUT_DIM; i += 256) { sL[i] = Wl[i]; sR[i] = Wr[i]; }
    if (t < OUT_DIM) sb[t] = b[t];
    __syncthreads();

    int col  = t & 63;
    int wy   = t >> 6;                  // 0..3
    int row0 = blockIdx.x * 16 + wy * 4;

    float acc[4], inv[4];
#pragma unroll
    for (int r = 0; r < 4; r++) {
        acc[r] = sb[col];
        inv[r] = 1.0f / fmaxf(g_cnt[row0 + r], 1.0f);
    }
#pragma unroll 4
    for (int k = 0; k < HID; k++) {
        float wl = sL[k * OUT_DIM + col];
        float wr = sR[k * OUT_DIM + col];
#pragma unroll
        for (int r = 0; r < 4; r++) {
            float am = g_agg2[(row0 + r) * HID + k] * inv[r];  // warp-uniform
            float hv = g_h[(row0 + r) * HID + k];              // warp-uniform
            acc[r] += am * wl + hv * wr;
        }
    }
#pragma unroll
    for (int r = 0; r < 4; r++)
        out[(row0 + r) * OUT_DIM + col] = acc[r];
}

// ---------------------------------------------------------------------------
extern "C" void kernel_launch(void* const* d_in, const int* in_sizes, int n_in,
                              void* d_out, int out_size) {
    const float* x   = (const float*)d_in[0];
    const int*   ei  = (const int*)d_in[1];
    const float* W1l = (const float*)d_in[2];
    const float* W1r = (const float*)d_in[3];
    const float* b1  = (const float*)d_in[4];
    const float* W2l = (const float*)d_in[5];
    const float* W2r = (const float*)d_in[6];
    const float* b2  = (const float*)d_in[7];
    float* out = (float*)d_out;

    k_zero<<<2048, 256>>>();
    k_gemm1<<<(N_NODES + 31) / 32, 256>>>(x, W1l, W1r, b1);
    k_scatter1<<<(N_EDGES * 8 + 255) / 256, 256>>>(ei);
    k_finish1<<<2048, 256>>>();
    k_scatter2<<<(N_EDGES * 8 + 255) / 256, 256>>>(ei);
    k_gemm2_final<<<N_NODES / 16, 256>>>(W2l, W2r, b2, out);
}